// round 4
// baseline (speedup 1.0000x reference)
#include <cuda_runtime.h>
#include <math.h>

typedef unsigned long long u64;

__device__ __forceinline__ u64 f2pk(float lo, float hi) {
    u64 r; asm("mov.b64 %0,{%1,%2};" : "=l"(r) : "f"(lo), "f"(hi)); return r;
}
__device__ __forceinline__ void f2upk(u64 a, float& lo, float& hi) {
    asm("mov.b64 {%0,%1},%2;" : "=f"(lo), "=f"(hi) : "l"(a));
}
__device__ __forceinline__ u64 f2add(u64 a, u64 b) {
    u64 d; asm("add.rn.f32x2 %0,%1,%2;" : "=l"(d) : "l"(a), "l"(b)); return d;
}
__device__ __forceinline__ u64 f2mul(u64 a, u64 b) {
    u64 d; asm("mul.rn.f32x2 %0,%1,%2;" : "=l"(d) : "l"(a), "l"(b)); return d;
}
__device__ __forceinline__ u64 f2fma(u64 a, u64 b, u64 c) {
    u64 d; asm("fma.rn.f32x2 %0,%1,%2,%3;" : "=l"(d) : "l"(a), "l"(b), "l"(c)); return d;
}

// Scratch for MLP output z (anchor points): 32768 samples x 8 floats = 1 MB.
__device__ float g_z[32768 * 8];

// ================= Kernel 1: MLP 6->20->20->20->8 tanh, 1 sample/thread ==============
__global__ void __launch_bounds__(128, 1) mlp_kernel(
    const float* __restrict__ X,
    const float* __restrict__ W1, const float* __restrict__ b1,
    const float* __restrict__ W2, const float* __restrict__ b2,
    const float* __restrict__ W3, const float* __restrict__ b3,
    const float* __restrict__ W4, const float* __restrict__ b4, int B)
{
    __shared__ __align__(16) float sW1[120];
    __shared__ __align__(16) float sW2[400];
    __shared__ __align__(16) float sW3[400];
    __shared__ __align__(16) float sW4[160];
    __shared__ float sb1[20], sb2[20], sb3[20], sb4[8];

    const int t = threadIdx.x;
    for (int i = t; i < 120; i += 128) sW1[i] = W1[i];
    for (int i = t; i < 400; i += 128) sW2[i] = W2[i];
    for (int i = t; i < 400; i += 128) sW3[i] = W3[i];
    for (int i = t; i < 160; i += 128) sW4[i] = W4[i];
    if (t < 20) { sb1[t] = b1[t]; sb2[t] = b2[t]; sb3[t] = b3[t]; }
    if (t < 8)  { sb4[t] = b4[t]; }
    __syncthreads();

    const int idx = blockIdx.x * 128 + t;
    if (idx >= B) return;

    float Z[6];
    {
        const float2* Xp = reinterpret_cast<const float2*>(X + (size_t)idx * 6);
        float2 a0 = Xp[0], a1 = Xp[1], a2 = Xp[2];
        Z[0] = a0.x; Z[1] = a0.y; Z[2] = a1.x; Z[3] = a1.y; Z[4] = a2.x; Z[5] = a2.y;
    }

    float h1[20], h2[20];
#pragma unroll
    for (int o = 0; o < 20; ++o) {
        const float2* w = reinterpret_cast<const float2*>(&sW1[o * 6]);
        float2 w0 = w[0], w1 = w[1], w2 = w[2];
        float a = sb1[o];
        a = fmaf(w0.x, Z[0], a); a = fmaf(w0.y, Z[1], a);
        a = fmaf(w1.x, Z[2], a); a = fmaf(w1.y, Z[3], a);
        a = fmaf(w2.x, Z[4], a); a = fmaf(w2.y, Z[5], a);
        h1[o] = tanhf(a);
    }
#pragma unroll
    for (int o = 0; o < 20; ++o) {
        const float4* w = reinterpret_cast<const float4*>(&sW2[o * 20]);
        float a = sb2[o];
#pragma unroll
        for (int q = 0; q < 5; ++q) {
            float4 wq = w[q];
            a = fmaf(wq.x, h1[q * 4 + 0], a);
            a = fmaf(wq.y, h1[q * 4 + 1], a);
            a = fmaf(wq.z, h1[q * 4 + 2], a);
            a = fmaf(wq.w, h1[q * 4 + 3], a);
        }
        h2[o] = tanhf(a);
    }
#pragma unroll
    for (int o = 0; o < 20; ++o) {
        const float4* w = reinterpret_cast<const float4*>(&sW3[o * 20]);
        float a = sb3[o];
#pragma unroll
        for (int q = 0; q < 5; ++q) {
            float4 wq = w[q];
            a = fmaf(wq.x, h2[q * 4 + 0], a);
            a = fmaf(wq.y, h2[q * 4 + 1], a);
            a = fmaf(wq.z, h2[q * 4 + 2], a);
            a = fmaf(wq.w, h2[q * 4 + 3], a);
        }
        h1[o] = tanhf(a);
    }
    float z[8];
#pragma unroll
    for (int o = 0; o < 8; ++o) {
        const float4* w = reinterpret_cast<const float4*>(&sW4[o * 20]);
        float a = sb4[o];
#pragma unroll
        for (int q = 0; q < 5; ++q) {
            float4 wq = w[q];
            a = fmaf(wq.x, h1[q * 4 + 0], a);
            a = fmaf(wq.y, h1[q * 4 + 1], a);
            a = fmaf(wq.z, h1[q * 4 + 2], a);
            a = fmaf(wq.w, h1[q * 4 + 3], a);
        }
        z[o] = tanhf(a);
    }

    float4* zp = reinterpret_cast<float4*>(g_z + (size_t)idx * 8);
    zp[0] = make_float4(z[0], z[1], z[2], z[3]);
    zp[1] = make_float4(z[4], z[5], z[6], z[7]);
}

// ================= Kernel 2: PDHG QP, 2 samples/thread, packed f32x2 ==============
__global__ void __launch_bounds__(64, 1) qp_kernel(
    const float* __restrict__ X, float* __restrict__ out, int B)
{
    const int half = B >> 1;
    const int i0 = blockIdx.x * 64 + threadIdx.x;
    if (i0 >= half) return;
    const int i1 = i0 + half;

    const float tau  = 0.9f / sqrtf(26.0f);
    const float tau2 = tau * tau;
    const u64 NEG1 = 0xBF800000BF800000ULL;
    const u64 NT2  = f2pk(-tau2, -tau2);

    u64 zp[2][4], czp[2][4], sb2p[2][3], xp[2][4], l2p[2][4];
    float m[2][6];

#pragma unroll
    for (int s = 0; s < 2; ++s) {
        const int id = (s == 0) ? i0 : i1;
        const float2* Xp = reinterpret_cast<const float2*>(X + (size_t)id * 6);
        float2 a0 = Xp[0], a1 = Xp[1], a2 = Xp[2];
        sb2p[s][0] = f2pk(tau2 * a0.x, tau2 * a0.y);
        sb2p[s][1] = f2pk(tau2 * a1.x, tau2 * a1.y);
        sb2p[s][2] = f2pk(tau2 * a2.x, tau2 * a2.y);

        const float4* Zp = reinterpret_cast<const float4*>(g_z + (size_t)id * 8);
        float4 z0 = Zp[0], z1 = Zp[1];
        float zv[8] = { z0.x, z0.y, z0.z, z0.w, z1.x, z1.y, z1.z, z1.w };
#pragma unroll
        for (int k = 0; k < 4; ++k) {
            float zl = zv[2 * k], zh = zv[2 * k + 1];
            zp[s][k]  = f2pk(zl, zh);
            czp[s][k] = f2pk(tau - zl, tau - zh);
            xp[s][k]  = f2pk(fmaxf(zl, 0.0f), fmaxf(zh, 0.0f));
            l2p[s][k] = 0ULL;
        }
#pragma unroll
        for (int i = 0; i < 6; ++i) m[s][i] = 0.0f;
    }

#pragma unroll 1
    for (int it = 0; it < 150; ++it) {
#pragma unroll
        for (int s = 0; s < 2; ++s) {
            float m0 = m[s][0], m1 = m[s][1], m2 = m[s][2];
            float m3 = m[s][3], m4 = m[s][4], m5 = m[s][5];

            // sv'' = -tau * S^T l1 (<=0), packed pairs
            // cols: 0:{0,3} 1:{1,4} 2:{2,5} 3:{0,1,5} 4:{2,3,5} 5:{0,3} 6:{1,4} 7:{2,4}
            u64 s01 = f2add(f2pk(m0, m1), f2pk(m3, m4));       // (sv0, sv1)
            float t01 = m0 + m1;
            u64 s23 = f2add(f2pk(m2, t01), f2pk(m5, m5));      // (sv2, sv3)
            float t23 = m2 + m3;
            float sv4 = t23 + m5;
            float sv0, sv1; f2upk(s01, sv0, sv1);
            u64 s45 = f2pk(sv4, sv0);                          // (sv4, sv5=sv0)
            u64 s67 = f2add(f2pk(m1, m2), f2pk(m4, m4));       // (sv6=sv1, sv7)

            // v = (x + cz) + (L2' + sv'')
            u64 v0 = f2add(f2add(xp[s][0], czp[s][0]), f2add(l2p[s][0], s01));
            u64 v1 = f2add(f2add(xp[s][1], czp[s][1]), f2add(l2p[s][1], s23));
            u64 v2 = f2add(f2add(xp[s][2], czp[s][2]), f2add(l2p[s][2], s45));
            u64 v3 = f2add(f2add(xp[s][3], czp[s][3]), f2add(l2p[s][3], s67));

            // ||v||^2
            u64 nm = f2mul(v0, v0);
            nm = f2fma(v1, v1, nm);
            nm = f2fma(v2, v2, nm);
            nm = f2fma(v3, v3, nm);
            float na, nb; f2upk(nm, na, nb);
            float ss = na + nb;

            float r = rsqrtf(ss);
            float scale = fmaxf(fmaf(-tau, r, 1.0f), 0.0f);
            u64 sc2 = f2pk(scale, scale);

            // xn = z + scale*v ; xb = 2*xn - x
            u64 xn0 = f2fma(v0, sc2, zp[s][0]);
            u64 xn1 = f2fma(v1, sc2, zp[s][1]);
            u64 xn2 = f2fma(v2, sc2, zp[s][2]);
            u64 xn3 = f2fma(v3, sc2, zp[s][3]);
            u64 xb0 = f2add(xn0, f2fma(xp[s][0], NEG1, xn0));
            u64 xb1 = f2add(xn1, f2fma(xp[s][1], NEG1, xn1));
            u64 xb2 = f2add(xn2, f2fma(xp[s][2], NEG1, xn2));
            u64 xb3 = f2add(xn3, f2fma(xp[s][3], NEG1, xn3));
            xp[s][0] = xn0; xp[s][1] = xn1; xp[s][2] = xn2; xp[s][3] = xn3;

            float e0, e1, e2, e3, e4, e5, e6, e7;
            f2upk(xb0, e0, e1); f2upk(xb1, e2, e3);
            f2upk(xb2, e4, e5); f2upk(xb3, e6, e7);

            // rr = S @ xb, rows: 0:{0,3,5} 1:{1,3,6} 2:{2,4,7} 3:{0,4,5} 4:{1,6,7} 5:{2,3,4}
            u64 pp = f2add(xb0, f2pk(e5, e6));                 // (p05, p16)
            float p05, p16; f2upk(pp, p05, p16);
            float p24 = e2 + e4;
            u64 rr01 = f2add(pp, f2pk(e3, e3));                // (rr0, rr1)
            u64 rr23 = f2add(f2pk(p24, p05), f2pk(e7, e4));    // (rr2, rr3)
            u64 rr45 = f2add(f2pk(p16, p24), f2pk(e7, e3));    // (rr4, rr5)

            // l1 dual (negated, scaled): m = min(m - tau2*rr + tau2*b, 0)
            u64 u01 = f2add(f2fma(rr01, NT2, f2pk(m0, m1)), sb2p[s][0]);
            u64 u23 = f2add(f2fma(rr23, NT2, f2pk(m2, m3)), sb2p[s][1]);
            u64 u45 = f2add(f2fma(rr45, NT2, f2pk(m4, m5)), sb2p[s][2]);
            float q0, q1, q2, q3, q4, q5;
            f2upk(u01, q0, q1); f2upk(u23, q2, q3); f2upk(u45, q4, q5);
            m[s][0] = fminf(q0, 0.0f); m[s][1] = fminf(q1, 0.0f);
            m[s][2] = fminf(q2, 0.0f); m[s][3] = fminf(q3, 0.0f);
            m[s][4] = fminf(q4, 0.0f); m[s][5] = fminf(q5, 0.0f);

            // l2 dual (scaled): L2' = max(L2' - tau2*xb, 0)
            {
                u64 w0 = f2fma(xb0, NT2, l2p[s][0]);
                u64 w1 = f2fma(xb1, NT2, l2p[s][1]);
                u64 w2 = f2fma(xb2, NT2, l2p[s][2]);
                u64 w3 = f2fma(xb3, NT2, l2p[s][3]);
                float a, b;
                f2upk(w0, a, b); l2p[s][0] = f2pk(fmaxf(a, 0.f), fmaxf(b, 0.f));
                f2upk(w1, a, b); l2p[s][1] = f2pk(fmaxf(a, 0.f), fmaxf(b, 0.f));
                f2upk(w2, a, b); l2p[s][2] = f2pk(fmaxf(a, 0.f), fmaxf(b, 0.f));
                f2upk(w3, a, b); l2p[s][3] = f2pk(fmaxf(a, 0.f), fmaxf(b, 0.f));
            }
        }
    }

#pragma unroll
    for (int s = 0; s < 2; ++s) {
        const int id = (s == 0) ? i0 : i1;
        float o0, o1, o2, o3, o4, o5, o6, o7;
        f2upk(xp[s][0], o0, o1); f2upk(xp[s][1], o2, o3);
        f2upk(xp[s][2], o4, o5); f2upk(xp[s][3], o6, o7);
        float4* op = reinterpret_cast<float4*>(out + (size_t)id * 8);
        op[0] = make_float4(o0, o1, o2, o3);
        op[1] = make_float4(o4, o5, o6, o7);
    }
}

extern "C" void kernel_launch(void* const* d_in, const int* in_sizes, int n_in,
                              void* d_out, int out_size)
{
    const float* X  = (const float*)d_in[0];
    const float* W1 = (const float*)d_in[1];
    const float* b1 = (const float*)d_in[2];
    const float* W2 = (const float*)d_in[3];
    const float* b2 = (const float*)d_in[4];
    const float* W3 = (const float*)d_in[5];
    const float* b3 = (const float*)d_in[6];
    const float* W4 = (const float*)d_in[7];
    const float* b4 = (const float*)d_in[8];

    const int B = in_sizes[0] / 6;
    float* out = (float*)d_out;

    mlp_kernel<<<(B + 127) / 128, 128>>>(X, W1, b1, W2, b2, W3, b3, W4, b4, B);

    const int threads = B / 2;             // 2 samples per thread
    qp_kernel<<<(threads + 63) / 64, 64>>>(X, out, B);
}

// round 5
// speedup vs baseline: 1.0016x; 1.0016x over previous
#include <cuda_runtime.h>
#include <math.h>

// QP state for one sample: everything scalar, fully register-resident.
struct QP {
    float x[8], l1[6], l2[8];
    float z[8], cz[8], sbb[6];
};

// One PDHG iteration. Unscaled duals; multiplies by literal TAU / 2.0f hit
// the FFMA-imm (rt=1) form. If CHECK, accumulate bitwise state change into d
// (exit is exact: bit-identical state => all future iterations are no-ops).
template<bool CHECK>
__device__ __forceinline__ void qp_step(QP& q, unsigned& d) {
    const float TAU = 0.9f / sqrtf(26.0f);

    // v_j = (x_j + cz_j) + TAU*l2_j - TAU*(S^T l1)_j, S^T folded as fma-imm chains
    // cols: 0:{0,3} 1:{1,4} 2:{2,5} 3:{0,1,5} 4:{2,3,5} 5:{0,3} 6:{1,4} 7:{2,4}
    float v[8];
    {
        float t;
        t = q.x[0] + q.cz[0]; t = fmaf(TAU, q.l2[0], t);
        t = fmaf(-TAU, q.l1[0], t); v[0] = fmaf(-TAU, q.l1[3], t);
        t = q.x[1] + q.cz[1]; t = fmaf(TAU, q.l2[1], t);
        t = fmaf(-TAU, q.l1[1], t); v[1] = fmaf(-TAU, q.l1[4], t);
        t = q.x[2] + q.cz[2]; t = fmaf(TAU, q.l2[2], t);
        t = fmaf(-TAU, q.l1[2], t); v[2] = fmaf(-TAU, q.l1[5], t);
        t = q.x[3] + q.cz[3]; t = fmaf(TAU, q.l2[3], t);
        t = fmaf(-TAU, q.l1[0], t); t = fmaf(-TAU, q.l1[1], t); v[3] = fmaf(-TAU, q.l1[5], t);
        t = q.x[4] + q.cz[4]; t = fmaf(TAU, q.l2[4], t);
        t = fmaf(-TAU, q.l1[2], t); t = fmaf(-TAU, q.l1[3], t); v[4] = fmaf(-TAU, q.l1[5], t);
        t = q.x[5] + q.cz[5]; t = fmaf(TAU, q.l2[5], t);
        t = fmaf(-TAU, q.l1[0], t); v[5] = fmaf(-TAU, q.l1[3], t);
        t = q.x[6] + q.cz[6]; t = fmaf(TAU, q.l2[6], t);
        t = fmaf(-TAU, q.l1[1], t); v[6] = fmaf(-TAU, q.l1[4], t);
        t = q.x[7] + q.cz[7]; t = fmaf(TAU, q.l2[7], t);
        t = fmaf(-TAU, q.l1[2], t); v[7] = fmaf(-TAU, q.l1[4], t);
    }

    // ||v||^2 (two chains for latency balance)
    float c0 = v[0] * v[0];
    c0 = fmaf(v[1], v[1], c0); c0 = fmaf(v[2], v[2], c0); c0 = fmaf(v[3], v[3], c0);
    float c1 = v[4] * v[4];
    c1 = fmaf(v[5], v[5], c1); c1 = fmaf(v[6], v[6], c1); c1 = fmaf(v[7], v[7], c1);
    float ss = c0 + c1;

    // scale = max(1 - TAU/||v||, 0); rsqrt(0)=inf clamps to 0 like reference guard
    float scale = fmaxf(fmaf(-TAU, rsqrtf(ss), 1.0f), 0.0f);

    // x_new = z + scale*v ; xbar = 2*x_new - x
    float xb[8];
#pragma unroll
    for (int j = 0; j < 8; ++j) {
        float xn = fmaf(scale, v[j], q.z[j]);
        xb[j] = fmaf(2.0f, xn, -q.x[j]);
        if (CHECK) d |= __float_as_uint(xn) ^ __float_as_uint(q.x[j]);
        q.x[j] = xn;
    }

    // l1_i = max(l1_i + TAU*(S xbar)_i - TAU*b_i, 0), S rows folded as fma-imm
    // rows: 0:{0,3,5} 1:{1,3,6} 2:{2,4,7} 3:{0,4,5} 4:{1,6,7} 5:{2,3,4}
    {
        float u, ln;
        u = q.l1[0] - q.sbb[0];
        u = fmaf(TAU, xb[0], u); u = fmaf(TAU, xb[3], u); u = fmaf(TAU, xb[5], u);
        ln = fmaxf(u, 0.0f);
        if (CHECK) d |= __float_as_uint(ln) ^ __float_as_uint(q.l1[0]);
        q.l1[0] = ln;

        u = q.l1[1] - q.sbb[1];
        u = fmaf(TAU, xb[1], u); u = fmaf(TAU, xb[3], u); u = fmaf(TAU, xb[6], u);
        ln = fmaxf(u, 0.0f);
        if (CHECK) d |= __float_as_uint(ln) ^ __float_as_uint(q.l1[1]);
        q.l1[1] = ln;

        u = q.l1[2] - q.sbb[2];
        u = fmaf(TAU, xb[2], u); u = fmaf(TAU, xb[4], u); u = fmaf(TAU, xb[7], u);
        ln = fmaxf(u, 0.0f);
        if (CHECK) d |= __float_as_uint(ln) ^ __float_as_uint(q.l1[2]);
        q.l1[2] = ln;

        u = q.l1[3] - q.sbb[3];
        u = fmaf(TAU, xb[0], u); u = fmaf(TAU, xb[4], u); u = fmaf(TAU, xb[5], u);
        ln = fmaxf(u, 0.0f);
        if (CHECK) d |= __float_as_uint(ln) ^ __float_as_uint(q.l1[3]);
        q.l1[3] = ln;

        u = q.l1[4] - q.sbb[4];
        u = fmaf(TAU, xb[1], u); u = fmaf(TAU, xb[6], u); u = fmaf(TAU, xb[7], u);
        ln = fmaxf(u, 0.0f);
        if (CHECK) d |= __float_as_uint(ln) ^ __float_as_uint(q.l1[4]);
        q.l1[4] = ln;

        u = q.l1[5] - q.sbb[5];
        u = fmaf(TAU, xb[2], u); u = fmaf(TAU, xb[3], u); u = fmaf(TAU, xb[4], u);
        ln = fmaxf(u, 0.0f);
        if (CHECK) d |= __float_as_uint(ln) ^ __float_as_uint(q.l1[5]);
        q.l1[5] = ln;
    }

    // l2_j = max(l2_j - TAU*xbar_j, 0)
#pragma unroll
    for (int j = 0; j < 8; ++j) {
        float w = fmaf(-TAU, xb[j], q.l2[j]);
        float ln = fmaxf(w, 0.0f);
        if (CHECK) d |= __float_as_uint(ln) ^ __float_as_uint(q.l2[j]);
        q.l2[j] = ln;
    }
}

// MLP 6->20->20->20->8, tanh. Weights in smem.
__device__ __forceinline__ void mlp(const float Z[6], float z[8],
    const float* sW1, const float* sb1, const float* sW2, const float* sb2,
    const float* sW3, const float* sb3, const float* sW4, const float* sb4)
{
    float h1[20], h2[20];
#pragma unroll
    for (int o = 0; o < 20; ++o) {
        const float2* w = reinterpret_cast<const float2*>(&sW1[o * 6]);
        float2 w0 = w[0], w1 = w[1], w2 = w[2];
        float a = sb1[o];
        a = fmaf(w0.x, Z[0], a); a = fmaf(w0.y, Z[1], a);
        a = fmaf(w1.x, Z[2], a); a = fmaf(w1.y, Z[3], a);
        a = fmaf(w2.x, Z[4], a); a = fmaf(w2.y, Z[5], a);
        h1[o] = tanhf(a);
    }
#pragma unroll
    for (int o = 0; o < 20; ++o) {
        const float4* w = reinterpret_cast<const float4*>(&sW2[o * 20]);
        float a = sb2[o];
#pragma unroll
        for (int q = 0; q < 5; ++q) {
            float4 wq = w[q];
            a = fmaf(wq.x, h1[q * 4 + 0], a);
            a = fmaf(wq.y, h1[q * 4 + 1], a);
            a = fmaf(wq.z, h1[q * 4 + 2], a);
            a = fmaf(wq.w, h1[q * 4 + 3], a);
        }
        h2[o] = tanhf(a);
    }
#pragma unroll
    for (int o = 0; o < 20; ++o) {
        const float4* w = reinterpret_cast<const float4*>(&sW3[o * 20]);
        float a = sb3[o];
#pragma unroll
        for (int q = 0; q < 5; ++q) {
            float4 wq = w[q];
            a = fmaf(wq.x, h2[q * 4 + 0], a);
            a = fmaf(wq.y, h2[q * 4 + 1], a);
            a = fmaf(wq.z, h2[q * 4 + 2], a);
            a = fmaf(wq.w, h2[q * 4 + 3], a);
        }
        h1[o] = tanhf(a);
    }
#pragma unroll
    for (int o = 0; o < 8; ++o) {
        const float4* w = reinterpret_cast<const float4*>(&sW4[o * 20]);
        float a = sb4[o];
#pragma unroll
        for (int q = 0; q < 5; ++q) {
            float4 wq = w[q];
            a = fmaf(wq.x, h1[q * 4 + 0], a);
            a = fmaf(wq.y, h1[q * 4 + 1], a);
            a = fmaf(wq.z, h1[q * 4 + 2], a);
            a = fmaf(wq.w, h1[q * 4 + 3], a);
        }
        z[o] = tanhf(a);
    }
}

__global__ void __launch_bounds__(64, 1) matchnet_kernel(
    const float* __restrict__ X,
    const float* __restrict__ W1, const float* __restrict__ b1,
    const float* __restrict__ W2, const float* __restrict__ b2,
    const float* __restrict__ W3, const float* __restrict__ b3,
    const float* __restrict__ W4, const float* __restrict__ b4,
    float* __restrict__ out, int B)
{
    __shared__ __align__(16) float sW1[120];
    __shared__ __align__(16) float sW2[400];
    __shared__ __align__(16) float sW3[400];
    __shared__ __align__(16) float sW4[160];
    __shared__ float sb1[20], sb2s[20], sb3[20], sb4[8];

    const int t = threadIdx.x;
    for (int i = t; i < 120; i += 64) sW1[i] = W1[i];
    for (int i = t; i < 400; i += 64) sW2[i] = W2[i];
    for (int i = t; i < 400; i += 64) sW3[i] = W3[i];
    for (int i = t; i < 160; i += 64) sW4[i] = W4[i];
    if (t < 20) { sb1[t] = b1[t]; sb2s[t] = b2[t]; sb3[t] = b3[t]; }
    if (t < 8)  { sb4[t] = b4[t]; }
    __syncthreads();

    const int half = B >> 1;
    const int i0 = blockIdx.x * 64 + t;
    if (i0 >= half) return;
    const int i1 = i0 + half;

    const float TAU = 0.9f / sqrtf(26.0f);

    QP qa, qb;

    // ---- load bids + MLPs + QP init, both samples ----
#pragma unroll
    for (int s = 0; s < 2; ++s) {
        QP& q = (s == 0) ? qa : qb;
        const int id = (s == 0) ? i0 : i1;

        float Z[6];
        const float2* Xp = reinterpret_cast<const float2*>(X + (size_t)id * 6);
        float2 a0 = Xp[0], a1 = Xp[1], a2 = Xp[2];
        Z[0] = a0.x; Z[1] = a0.y; Z[2] = a1.x; Z[3] = a1.y; Z[4] = a2.x; Z[5] = a2.y;

        float z[8];
        mlp(Z, z, sW1, sb1, sW2, sb2s, sW3, sb3, sW4, sb4);

#pragma unroll
        for (int j = 0; j < 8; ++j) {
            q.z[j]  = z[j];
            q.cz[j] = TAU - z[j];
            q.x[j]  = fmaxf(z[j], 0.0f);
            q.l2[j] = 0.0f;
        }
#pragma unroll
        for (int i = 0; i < 6; ++i) { q.l1[i] = 0.0f; q.sbb[i] = TAU * Z[i]; }
    }

    // ---- PDHG: 2 plain iterations + 37 blocks of (3 plain + 1 checked) = 150 ----
    unsigned dd = 0;
    qp_step<false>(qa, dd); qp_step<false>(qb, dd);
    qp_step<false>(qa, dd); qp_step<false>(qb, dd);

#pragma unroll 1
    for (int blk = 0; blk < 37; ++blk) {
        qp_step<false>(qa, dd); qp_step<false>(qb, dd);
        qp_step<false>(qa, dd); qp_step<false>(qb, dd);
        qp_step<false>(qa, dd); qp_step<false>(qb, dd);
        unsigned d = 0;
        qp_step<true>(qa, d); qp_step<true>(qb, d);
        // Exact fixed point for every lane of the warp: all remaining
        // iterations would be bit-identical no-ops -> safe to stop.
        if (__all_sync(0xFFFFFFFFu, d == 0u)) break;
    }

    // ---- store ----
#pragma unroll
    for (int s = 0; s < 2; ++s) {
        QP& q = (s == 0) ? qa : qb;
        const int id = (s == 0) ? i0 : i1;
        float4* op = reinterpret_cast<float4*>(out + (size_t)id * 8);
        op[0] = make_float4(q.x[0], q.x[1], q.x[2], q.x[3]);
        op[1] = make_float4(q.x[4], q.x[5], q.x[6], q.x[7]);
    }
}

extern "C" void kernel_launch(void* const* d_in, const int* in_sizes, int n_in,
                              void* d_out, int out_size)
{
    const float* X  = (const float*)d_in[0];
    const float* W1 = (const float*)d_in[1];
    const float* b1 = (const float*)d_in[2];
    const float* W2 = (const float*)d_in[3];
    const float* b2 = (const float*)d_in[4];
    const float* W3 = (const float*)d_in[5];
    const float* b3 = (const float*)d_in[6];
    const float* W4 = (const float*)d_in[7];
    const float* b4 = (const float*)d_in[8];

    const int B = in_sizes[0] / 6;
    float* out = (float*)d_out;

    const int threads = B / 2;               // 2 samples per thread
    const int block = 64;
    const int grid = (threads + block - 1) / block;
    matchnet_kernel<<<grid, block>>>(X, W1, b1, W2, b2, W3, b3, W4, b4, out, B);
}

// round 6
// speedup vs baseline: 1.1642x; 1.1623x over previous
#include <cuda_runtime.h>
#include <math.h>

// QP state for one sample: everything scalar, fully register-resident.
struct QP {
    float x[8], l1[6], l2[8];
    float z[8], cz[8], sbb[6];
};

// One PDHG iteration. Unscaled duals; multiplies by literal TAU / 2.0f are
// eligible for the FFMA-imm (rt=1) form. If CHECK, accumulate bitwise state
// change into d (exit is exact: bit-identical state => future iters no-op).
template<bool CHECK>
__device__ __forceinline__ void qp_step(QP& q, unsigned& d) {
    const float TAU = 0.9f / sqrtf(26.0f);

    // v_j = (x_j + cz_j) + TAU*l2_j - TAU*(S^T l1)_j
    // cols: 0:{0,3} 1:{1,4} 2:{2,5} 3:{0,1,5} 4:{2,3,5} 5:{0,3} 6:{1,4} 7:{2,4}
    float v[8];
    {
        float t;
        t = q.x[0] + q.cz[0]; t = fmaf(TAU, q.l2[0], t);
        t = fmaf(-TAU, q.l1[0], t); v[0] = fmaf(-TAU, q.l1[3], t);
        t = q.x[1] + q.cz[1]; t = fmaf(TAU, q.l2[1], t);
        t = fmaf(-TAU, q.l1[1], t); v[1] = fmaf(-TAU, q.l1[4], t);
        t = q.x[2] + q.cz[2]; t = fmaf(TAU, q.l2[2], t);
        t = fmaf(-TAU, q.l1[2], t); v[2] = fmaf(-TAU, q.l1[5], t);
        t = q.x[3] + q.cz[3]; t = fmaf(TAU, q.l2[3], t);
        t = fmaf(-TAU, q.l1[0], t); t = fmaf(-TAU, q.l1[1], t); v[3] = fmaf(-TAU, q.l1[5], t);
        t = q.x[4] + q.cz[4]; t = fmaf(TAU, q.l2[4], t);
        t = fmaf(-TAU, q.l1[2], t); t = fmaf(-TAU, q.l1[3], t); v[4] = fmaf(-TAU, q.l1[5], t);
        t = q.x[5] + q.cz[5]; t = fmaf(TAU, q.l2[5], t);
        t = fmaf(-TAU, q.l1[0], t); v[5] = fmaf(-TAU, q.l1[3], t);
        t = q.x[6] + q.cz[6]; t = fmaf(TAU, q.l2[6], t);
        t = fmaf(-TAU, q.l1[1], t); v[6] = fmaf(-TAU, q.l1[4], t);
        t = q.x[7] + q.cz[7]; t = fmaf(TAU, q.l2[7], t);
        t = fmaf(-TAU, q.l1[2], t); v[7] = fmaf(-TAU, q.l1[4], t);
    }

    // ||v||^2 (two chains for latency balance)
    float c0 = v[0] * v[0];
    c0 = fmaf(v[1], v[1], c0); c0 = fmaf(v[2], v[2], c0); c0 = fmaf(v[3], v[3], c0);
    float c1 = v[4] * v[4];
    c1 = fmaf(v[5], v[5], c1); c1 = fmaf(v[6], v[6], c1); c1 = fmaf(v[7], v[7], c1);
    float ss = c0 + c1;

    // scale = max(1 - TAU/||v||, 0); rsqrt(0)=inf clamps to 0 like reference guard
    float scale = fmaxf(fmaf(-TAU, rsqrtf(ss), 1.0f), 0.0f);

    // x_new = z + scale*v ; xbar = 2*x_new - x
    float xb[8];
#pragma unroll
    for (int j = 0; j < 8; ++j) {
        float xn = fmaf(scale, v[j], q.z[j]);
        xb[j] = fmaf(2.0f, xn, -q.x[j]);
        if (CHECK) d |= __float_as_uint(xn) ^ __float_as_uint(q.x[j]);
        q.x[j] = xn;
    }

    // l1_i = max(l1_i + TAU*(S xbar)_i - TAU*b_i, 0)
    // rows: 0:{0,3,5} 1:{1,3,6} 2:{2,4,7} 3:{0,4,5} 4:{1,6,7} 5:{2,3,4}
    {
        float u, ln;
        u = q.l1[0] - q.sbb[0];
        u = fmaf(TAU, xb[0], u); u = fmaf(TAU, xb[3], u); u = fmaf(TAU, xb[5], u);
        ln = fmaxf(u, 0.0f);
        if (CHECK) d |= __float_as_uint(ln) ^ __float_as_uint(q.l1[0]);
        q.l1[0] = ln;

        u = q.l1[1] - q.sbb[1];
        u = fmaf(TAU, xb[1], u); u = fmaf(TAU, xb[3], u); u = fmaf(TAU, xb[6], u);
        ln = fmaxf(u, 0.0f);
        if (CHECK) d |= __float_as_uint(ln) ^ __float_as_uint(q.l1[1]);
        q.l1[1] = ln;

        u = q.l1[2] - q.sbb[2];
        u = fmaf(TAU, xb[2], u); u = fmaf(TAU, xb[4], u); u = fmaf(TAU, xb[7], u);
        ln = fmaxf(u, 0.0f);
        if (CHECK) d |= __float_as_uint(ln) ^ __float_as_uint(q.l1[2]);
        q.l1[2] = ln;

        u = q.l1[3] - q.sbb[3];
        u = fmaf(TAU, xb[0], u); u = fmaf(TAU, xb[4], u); u = fmaf(TAU, xb[5], u);
        ln = fmaxf(u, 0.0f);
        if (CHECK) d |= __float_as_uint(ln) ^ __float_as_uint(q.l1[3]);
        q.l1[3] = ln;

        u = q.l1[4] - q.sbb[4];
        u = fmaf(TAU, xb[1], u); u = fmaf(TAU, xb[6], u); u = fmaf(TAU, xb[7], u);
        ln = fmaxf(u, 0.0f);
        if (CHECK) d |= __float_as_uint(ln) ^ __float_as_uint(q.l1[4]);
        q.l1[4] = ln;

        u = q.l1[5] - q.sbb[5];
        u = fmaf(TAU, xb[2], u); u = fmaf(TAU, xb[3], u); u = fmaf(TAU, xb[4], u);
        ln = fmaxf(u, 0.0f);
        if (CHECK) d |= __float_as_uint(ln) ^ __float_as_uint(q.l1[5]);
        q.l1[5] = ln;
    }

    // l2_j = max(l2_j - TAU*xbar_j, 0)
#pragma unroll
    for (int j = 0; j < 8; ++j) {
        float w = fmaf(-TAU, xb[j], q.l2[j]);
        float ln = fmaxf(w, 0.0f);
        if (CHECK) d |= __float_as_uint(ln) ^ __float_as_uint(q.l2[j]);
        q.l2[j] = ln;
    }
}

__global__ void __launch_bounds__(128, 1) matchnet_kernel(
    const float* __restrict__ X,
    const float* __restrict__ W1, const float* __restrict__ b1,
    const float* __restrict__ W2, const float* __restrict__ b2,
    const float* __restrict__ W3, const float* __restrict__ b3,
    const float* __restrict__ W4, const float* __restrict__ b4,
    float* __restrict__ out, int B)
{
    __shared__ __align__(16) float sW1[120];
    __shared__ __align__(16) float sW2[400];
    __shared__ __align__(16) float sW3[400];
    __shared__ __align__(16) float sW4[160];
    __shared__ float sb1[20], sb2s[20], sb3[20], sb4[8];

    const int t = threadIdx.x;
    for (int i = t; i < 120; i += 128) sW1[i] = W1[i];
    for (int i = t; i < 400; i += 128) sW2[i] = W2[i];
    for (int i = t; i < 400; i += 128) sW3[i] = W3[i];
    for (int i = t; i < 160; i += 128) sW4[i] = W4[i];
    if (t < 20) { sb1[t] = b1[t]; sb2s[t] = b2[t]; sb3[t] = b3[t]; }
    if (t < 8)  { sb4[t] = b4[t]; }
    __syncthreads();

    const int idx = blockIdx.x * 128 + t;
    if (idx >= B) return;

    // ---- load bids ----
    float Z[6];
    {
        const float2* Xp = reinterpret_cast<const float2*>(X + (size_t)idx * 6);
        float2 a0 = Xp[0], a1 = Xp[1], a2 = Xp[2];
        Z[0] = a0.x; Z[1] = a0.y; Z[2] = a1.x; Z[3] = a1.y; Z[4] = a2.x; Z[5] = a2.y;
    }

    // ---- MLP 6->20->20->20->8, tanh ----
    float h1[20], h2[20];
#pragma unroll
    for (int o = 0; o < 20; ++o) {
        const float2* w = reinterpret_cast<const float2*>(&sW1[o * 6]);
        float2 w0 = w[0], w1 = w[1], w2 = w[2];
        float a = sb1[o];
        a = fmaf(w0.x, Z[0], a); a = fmaf(w0.y, Z[1], a);
        a = fmaf(w1.x, Z[2], a); a = fmaf(w1.y, Z[3], a);
        a = fmaf(w2.x, Z[4], a); a = fmaf(w2.y, Z[5], a);
        h1[o] = tanhf(a);
    }
#pragma unroll
    for (int o = 0; o < 20; ++o) {
        const float4* w = reinterpret_cast<const float4*>(&sW2[o * 20]);
        float a = sb2s[o];
#pragma unroll
        for (int q = 0; q < 5; ++q) {
            float4 wq = w[q];
            a = fmaf(wq.x, h1[q * 4 + 0], a);
            a = fmaf(wq.y, h1[q * 4 + 1], a);
            a = fmaf(wq.z, h1[q * 4 + 2], a);
            a = fmaf(wq.w, h1[q * 4 + 3], a);
        }
        h2[o] = tanhf(a);
    }
#pragma unroll
    for (int o = 0; o < 20; ++o) {
        const float4* w = reinterpret_cast<const float4*>(&sW3[o * 20]);
        float a = sb3[o];
#pragma unroll
        for (int q = 0; q < 5; ++q) {
            float4 wq = w[q];
            a = fmaf(wq.x, h2[q * 4 + 0], a);
            a = fmaf(wq.y, h2[q * 4 + 1], a);
            a = fmaf(wq.z, h2[q * 4 + 2], a);
            a = fmaf(wq.w, h2[q * 4 + 3], a);
        }
        h1[o] = tanhf(a);
    }
    float z[8];
#pragma unroll
    for (int o = 0; o < 8; ++o) {
        const float4* w = reinterpret_cast<const float4*>(&sW4[o * 20]);
        float a = sb4[o];
#pragma unroll
        for (int q = 0; q < 5; ++q) {
            float4 wq = w[q];
            a = fmaf(wq.x, h1[q * 4 + 0], a);
            a = fmaf(wq.y, h1[q * 4 + 1], a);
            a = fmaf(wq.z, h1[q * 4 + 2], a);
            a = fmaf(wq.w, h1[q * 4 + 3], a);
        }
        z[o] = tanhf(a);
    }

    // ---- QP init ----
    const float TAU = 0.9f / sqrtf(26.0f);
    QP q;
#pragma unroll
    for (int j = 0; j < 8; ++j) {
        q.z[j]  = z[j];
        q.cz[j] = TAU - z[j];
        q.x[j]  = fmaxf(z[j], 0.0f);
        q.l2[j] = 0.0f;
    }
#pragma unroll
    for (int i = 0; i < 6; ++i) { q.l1[i] = 0.0f; q.sbb[i] = TAU * Z[i]; }

    // ---- PDHG: 2 plain iters + 37 blocks of (3 plain + 1 checked) = 150 ----
    unsigned dd = 0;
    qp_step<false>(q, dd);
    qp_step<false>(q, dd);

#pragma unroll 1
    for (int blk = 0; blk < 37; ++blk) {
        qp_step<false>(q, dd);
        qp_step<false>(q, dd);
        qp_step<false>(q, dd);
        unsigned d = 0;
        qp_step<true>(q, d);
        // Exact fixed point for every lane of the warp: all remaining
        // iterations would be bit-identical no-ops -> safe to stop.
        if (__all_sync(0xFFFFFFFFu, d == 0u)) break;
    }

    // ---- store ----
    float4* op = reinterpret_cast<float4*>(out + (size_t)idx * 8);
    op[0] = make_float4(q.x[0], q.x[1], q.x[2], q.x[3]);
    op[1] = make_float4(q.x[4], q.x[5], q.x[6], q.x[7]);
}

extern "C" void kernel_launch(void* const* d_in, const int* in_sizes, int n_in,
                              void* d_out, int out_size)
{
    const float* X  = (const float*)d_in[0];
    const float* W1 = (const float*)d_in[1];
    const float* b1 = (const float*)d_in[2];
    const float* W2 = (const float*)d_in[3];
    const float* b2 = (const float*)d_in[4];
    const float* W3 = (const float*)d_in[5];
    const float* b3 = (const float*)d_in[6];
    const float* W4 = (const float*)d_in[7];
    const float* b4 = (const float*)d_in[8];

    const int B = in_sizes[0] / 6;
    float* out = (float*)d_out;

    const int block = 128;
    const int grid = (B + block - 1) / block;
    matchnet_kernel<<<grid, block>>>(X, W1, b1, W2, b2, W3, b3, W4, b4, out, B);
}

// round 7
// speedup vs baseline: 1.1786x; 1.0124x over previous
#include <cuda_runtime.h>
#include <math.h>

typedef unsigned long long u64;

__device__ __forceinline__ u64 f2pk(float lo, float hi) {
    u64 r; asm("mov.b64 %0,{%1,%2};" : "=l"(r) : "f"(lo), "f"(hi)); return r;
}
__device__ __forceinline__ void f2upk(u64 a, float& lo, float& hi) {
    asm("mov.b64 {%0,%1},%2;" : "=f"(lo), "=f"(hi) : "l"(a));
}
__device__ __forceinline__ u64 f2add(u64 a, u64 b) {
    u64 d; asm("add.rn.f32x2 %0,%1,%2;" : "=l"(d) : "l"(a), "l"(b)); return d;
}
__device__ __forceinline__ u64 f2mul(u64 a, u64 b) {
    u64 d; asm("mul.rn.f32x2 %0,%1,%2;" : "=l"(d) : "l"(a), "l"(b)); return d;
}
__device__ __forceinline__ u64 f2fma(u64 a, u64 b, u64 c) {
    u64 d; asm("fma.rn.f32x2 %0,%1,%2,%3;" : "=l"(d) : "l"(a), "l"(b), "l"(c)); return d;
}

// Packed QP state (one sample): x, tau*l2 packed; m = -tau*l1 scalar.
struct QPP {
    u64 xp[4], l2p[4];       // state
    u64 zp[4], czp[4];       // constants
    u64 sb2p[3];             // tau^2 * b packed
    float m[6];              // -tau * l1
};

__device__ __forceinline__ void qp_iter(QPP& q) {
    const float tau  = 0.9f / sqrtf(26.0f);
    const float tau2 = tau * tau;
    const u64 NEG1 = 0xBF800000BF800000ULL;
    const u64 NT2  = f2pk(-tau2, -tau2);

    float m0 = q.m[0], m1 = q.m[1], m2 = q.m[2];
    float m3 = q.m[3], m4 = q.m[4], m5 = q.m[5];

    // sv'' = -tau * S^T l1 (<=0), packed pairs
    // cols: 0:{0,3} 1:{1,4} 2:{2,5} 3:{0,1,5} 4:{2,3,5} 5:{0,3} 6:{1,4} 7:{2,4}
    u64 s01 = f2add(f2pk(m0, m1), f2pk(m3, m4));       // (sv0, sv1)
    float t01 = m0 + m1;
    u64 s23 = f2add(f2pk(m2, t01), f2pk(m5, m5));      // (sv2, sv3)
    float t23 = m2 + m3;
    float sv4 = t23 + m5;
    float sv0, sv1; f2upk(s01, sv0, sv1);
    u64 s45 = f2pk(sv4, sv0);                          // (sv4, sv5=sv0)
    u64 s67 = f2add(f2pk(m1, m2), f2pk(m4, m4));       // (sv6=sv1, sv7)

    // v = (x + cz) + (L2' + sv'')
    u64 v0 = f2add(f2add(q.xp[0], q.czp[0]), f2add(q.l2p[0], s01));
    u64 v1 = f2add(f2add(q.xp[1], q.czp[1]), f2add(q.l2p[1], s23));
    u64 v2 = f2add(f2add(q.xp[2], q.czp[2]), f2add(q.l2p[2], s45));
    u64 v3 = f2add(f2add(q.xp[3], q.czp[3]), f2add(q.l2p[3], s67));

    // ||v||^2  (balanced tree: depth 3)
    u64 na_ = f2fma(v1, v1, f2mul(v0, v0));
    u64 nb_ = f2fma(v3, v3, f2mul(v2, v2));
    u64 nm  = f2add(na_, nb_);
    float na, nb; f2upk(nm, na, nb);
    float ss = na + nb;

    // scale = max(1 - tau/||v||, 0); rsqrt(0)=inf -> clamps to 0
    float r = rsqrtf(ss);
    float scale = fmaxf(fmaf(-tau, r, 1.0f), 0.0f);
    u64 sc2 = f2pk(scale, scale);

    // xn = z + scale*v ; xb = 2*xn - x
    u64 xn0 = f2fma(v0, sc2, q.zp[0]);
    u64 xn1 = f2fma(v1, sc2, q.zp[1]);
    u64 xn2 = f2fma(v2, sc2, q.zp[2]);
    u64 xn3 = f2fma(v3, sc2, q.zp[3]);
    u64 xb0 = f2add(xn0, f2fma(q.xp[0], NEG1, xn0));
    u64 xb1 = f2add(xn1, f2fma(q.xp[1], NEG1, xn1));
    u64 xb2 = f2add(xn2, f2fma(q.xp[2], NEG1, xn2));
    u64 xb3 = f2add(xn3, f2fma(q.xp[3], NEG1, xn3));
    q.xp[0] = xn0; q.xp[1] = xn1; q.xp[2] = xn2; q.xp[3] = xn3;

    float e0, e1, e2, e3, e4, e5, e6, e7;
    f2upk(xb0, e0, e1); f2upk(xb1, e2, e3);
    f2upk(xb2, e4, e5); f2upk(xb3, e6, e7);

    // rr = S @ xb, rows: 0:{0,3,5} 1:{1,3,6} 2:{2,4,7} 3:{0,4,5} 4:{1,6,7} 5:{2,3,4}
    u64 pp = f2add(xb0, f2pk(e5, e6));                 // (p05, p16)
    float p05, p16; f2upk(pp, p05, p16);
    float p24 = e2 + e4;
    u64 rr01 = f2add(pp, f2pk(e3, e3));                // (rr0, rr1)
    u64 rr23 = f2add(f2pk(p24, p05), f2pk(e7, e4));    // (rr2, rr3)
    u64 rr45 = f2add(f2pk(p16, p24), f2pk(e7, e3));    // (rr4, rr5)

    // l1 dual (negated, scaled): m = min(m - tau2*rr + tau2*b, 0)
    u64 u01 = f2add(f2fma(rr01, NT2, f2pk(m0, m1)), q.sb2p[0]);
    u64 u23 = f2add(f2fma(rr23, NT2, f2pk(m2, m3)), q.sb2p[1]);
    u64 u45 = f2add(f2fma(rr45, NT2, f2pk(m4, m5)), q.sb2p[2]);
    float q0, q1, q2, q3, q4, q5;
    f2upk(u01, q0, q1); f2upk(u23, q2, q3); f2upk(u45, q4, q5);
    q.m[0] = fminf(q0, 0.0f); q.m[1] = fminf(q1, 0.0f);
    q.m[2] = fminf(q2, 0.0f); q.m[3] = fminf(q3, 0.0f);
    q.m[4] = fminf(q4, 0.0f); q.m[5] = fminf(q5, 0.0f);

    // l2 dual (scaled): L2' = max(L2' - tau2*xb, 0)
    {
        u64 w0 = f2fma(xb0, NT2, q.l2p[0]);
        u64 w1 = f2fma(xb1, NT2, q.l2p[1]);
        u64 w2 = f2fma(xb2, NT2, q.l2p[2]);
        u64 w3 = f2fma(xb3, NT2, q.l2p[3]);
        float a, b;
        f2upk(w0, a, b); q.l2p[0] = f2pk(fmaxf(a, 0.f), fmaxf(b, 0.f));
        f2upk(w1, a, b); q.l2p[1] = f2pk(fmaxf(a, 0.f), fmaxf(b, 0.f));
        f2upk(w2, a, b); q.l2p[2] = f2pk(fmaxf(a, 0.f), fmaxf(b, 0.f));
        f2upk(w3, a, b); q.l2p[3] = f2pk(fmaxf(a, 0.f), fmaxf(b, 0.f));
    }
}

// Max |delta| between saved and current state (packed diffs, scalar abs/max).
__device__ __forceinline__ float qp_delta(const QPP& q,
    const u64 ox[4], const u64 ol[4], const float om[6])
{
    const u64 NEG1 = 0xBF800000BF800000ULL;
    float d = 0.f, a, b;
#pragma unroll
    for (int k = 0; k < 4; ++k) {
        u64 dx = f2fma(ox[k], NEG1, q.xp[k]);
        f2upk(dx, a, b);
        d = fmaxf(d, fmaxf(fabsf(a), fabsf(b)));
        u64 dl = f2fma(ol[k], NEG1, q.l2p[k]);
        f2upk(dl, a, b);
        d = fmaxf(d, fmaxf(fabsf(a), fabsf(b)));
    }
#pragma unroll
    for (int i = 0; i < 6; ++i) d = fmaxf(d, fabsf(q.m[i] - om[i]));
    return d;
}

__global__ void __launch_bounds__(256, 1) matchnet_kernel(
    const float* __restrict__ X,
    const float* __restrict__ W1, const float* __restrict__ b1,
    const float* __restrict__ W2, const float* __restrict__ b2,
    const float* __restrict__ W3, const float* __restrict__ b3,
    const float* __restrict__ W4, const float* __restrict__ b4,
    float* __restrict__ out, int B)
{
    __shared__ __align__(16) float sW1[120];
    __shared__ __align__(16) float sW2[400];
    __shared__ __align__(16) float sW3[400];
    __shared__ __align__(16) float sW4[160];
    __shared__ float sb1[20], sb2s[20], sb3[20], sb4[8];

    const int t = threadIdx.x;
    for (int i = t; i < 120; i += 256) sW1[i] = W1[i];
    for (int i = t; i < 400; i += 256) sW2[i] = W2[i];
    for (int i = t; i < 400; i += 256) sW3[i] = W3[i];
    for (int i = t; i < 160; i += 256) sW4[i] = W4[i];
    if (t < 20) { sb1[t] = b1[t]; sb2s[t] = b2[t]; sb3[t] = b3[t]; }
    if (t < 8)  { sb4[t] = b4[t]; }
    __syncthreads();

    const int idx = blockIdx.x * 256 + t;
    if (idx >= B) return;

    // ---- load bids ----
    float Z[6];
    {
        const float2* Xp = reinterpret_cast<const float2*>(X + (size_t)idx * 6);
        float2 a0 = Xp[0], a1 = Xp[1], a2 = Xp[2];
        Z[0] = a0.x; Z[1] = a0.y; Z[2] = a1.x; Z[3] = a1.y; Z[4] = a2.x; Z[5] = a2.y;
    }

    // ---- MLP 6->20->20->20->8, tanh ----
    float h1[20], h2[20];
#pragma unroll
    for (int o = 0; o < 20; ++o) {
        const float2* w = reinterpret_cast<const float2*>(&sW1[o * 6]);
        float2 w0 = w[0], w1 = w[1], w2 = w[2];
        float a = sb1[o];
        a = fmaf(w0.x, Z[0], a); a = fmaf(w0.y, Z[1], a);
        a = fmaf(w1.x, Z[2], a); a = fmaf(w1.y, Z[3], a);
        a = fmaf(w2.x, Z[4], a); a = fmaf(w2.y, Z[5], a);
        h1[o] = tanhf(a);
    }
#pragma unroll
    for (int o = 0; o < 20; ++o) {
        const float4* w = reinterpret_cast<const float4*>(&sW2[o * 20]);
        float a = sb2s[o];
#pragma unroll
        for (int qq = 0; qq < 5; ++qq) {
            float4 wq = w[qq];
            a = fmaf(wq.x, h1[qq * 4 + 0], a);
            a = fmaf(wq.y, h1[qq * 4 + 1], a);
            a = fmaf(wq.z, h1[qq * 4 + 2], a);
            a = fmaf(wq.w, h1[qq * 4 + 3], a);
        }
        h2[o] = tanhf(a);
    }
#pragma unroll
    for (int o = 0; o < 20; ++o) {
        const float4* w = reinterpret_cast<const float4*>(&sW3[o * 20]);
        float a = sb3[o];
#pragma unroll
        for (int qq = 0; qq < 5; ++qq) {
            float4 wq = w[qq];
            a = fmaf(wq.x, h2[qq * 4 + 0], a);
            a = fmaf(wq.y, h2[qq * 4 + 1], a);
            a = fmaf(wq.z, h2[qq * 4 + 2], a);
            a = fmaf(wq.w, h2[qq * 4 + 3], a);
        }
        h1[o] = tanhf(a);
    }
    float z[8];
#pragma unroll
    for (int o = 0; o < 8; ++o) {
        const float4* w = reinterpret_cast<const float4*>(&sW4[o * 20]);
        float a = sb4[o];
#pragma unroll
        for (int qq = 0; qq < 5; ++qq) {
            float4 wq = w[qq];
            a = fmaf(wq.x, h1[qq * 4 + 0], a);
            a = fmaf(wq.y, h1[qq * 4 + 1], a);
            a = fmaf(wq.z, h1[qq * 4 + 2], a);
            a = fmaf(wq.w, h1[qq * 4 + 3], a);
        }
        z[o] = tanhf(a);
    }

    // ---- QP init (packed, duals scaled by tau) ----
    const float tau  = 0.9f / sqrtf(26.0f);
    const float tau2 = tau * tau;

    QPP q;
#pragma unroll
    for (int k = 0; k < 4; ++k) {
        float zl = z[2 * k], zh = z[2 * k + 1];
        q.zp[k]  = f2pk(zl, zh);
        q.czp[k] = f2pk(tau - zl, tau - zh);
        q.xp[k]  = f2pk(fmaxf(zl, 0.0f), fmaxf(zh, 0.0f));
        q.l2p[k] = 0ULL;
    }
    q.sb2p[0] = f2pk(tau2 * Z[0], tau2 * Z[1]);
    q.sb2p[1] = f2pk(tau2 * Z[2], tau2 * Z[3]);
    q.sb2p[2] = f2pk(tau2 * Z[4], tau2 * Z[5]);
#pragma unroll
    for (int i = 0; i < 6; ++i) q.m[i] = 0.0f;

    // ---- PDHG: 22 plain iters + 16 blocks of (7 plain + 1 checked) = 150 ----
#pragma unroll 1
    for (int it = 0; it < 22; ++it) qp_iter(q);

#pragma unroll 1
    for (int blk = 0; blk < 16; ++blk) {
        qp_iter(q); qp_iter(q); qp_iter(q); qp_iter(q);
        qp_iter(q); qp_iter(q); qp_iter(q);
        // Checked iteration: snapshot, iterate, measure max state delta.
        u64 ox[4], ol[4]; float om[6];
#pragma unroll
        for (int k = 0; k < 4; ++k) { ox[k] = q.xp[k]; ol[k] = q.l2p[k]; }
#pragma unroll
        for (int i = 0; i < 6; ++i) om[i] = q.m[i];
        qp_iter(q);
        float d = qp_delta(q, ox, ol, om);
        // PDHG is non-expansive: per-iter change < 1e-7 for all 32 samples of
        // this warp bounds total remaining drift by ~150*1e-7 = 1.5e-5 << 1e-3.
        if (__all_sync(0xFFFFFFFFu, d < 1e-7f)) break;
    }

    // ---- store ----
    float o0, o1, o2, o3, o4, o5, o6, o7;
    f2upk(q.xp[0], o0, o1); f2upk(q.xp[1], o2, o3);
    f2upk(q.xp[2], o4, o5); f2upk(q.xp[3], o6, o7);
    float4* op = reinterpret_cast<float4*>(out + (size_t)idx * 8);
    op[0] = make_float4(o0, o1, o2, o3);
    op[1] = make_float4(o4, o5, o6, o7);
}

extern "C" void kernel_launch(void* const* d_in, const int* in_sizes, int n_in,
                              void* d_out, int out_size)
{
    const float* X  = (const float*)d_in[0];
    const float* W1 = (const float*)d_in[1];
    const float* b1 = (const float*)d_in[2];
    const float* W2 = (const float*)d_in[3];
    const float* b2 = (const float*)d_in[4];
    const float* W3 = (const float*)d_in[5];
    const float* b3 = (const float*)d_in[6];
    const float* W4 = (const float*)d_in[7];
    const float* b4 = (const float*)d_in[8];

    const int B = in_sizes[0] / 6;
    float* out = (float*)d_out;

    // block=256, grid=128: every busy SM gets exactly one block -> uniform
    // 2 warps/SMSP (removes the 1-warp-SMSP straggler tail of grid=256/128).
    const int block = 256;
    const int grid = (B + block - 1) / block;
    matchnet_kernel<<<grid, block>>>(X, W1, b1, W2, b2, W3, b3, W4, b4, out, B);
}

// round 8
// speedup vs baseline: 1.1981x; 1.0165x over previous
#include <cuda_runtime.h>
#include <math.h>

typedef unsigned long long u64;

__device__ __forceinline__ u64 f2pk(float lo, float hi) {
    u64 r; asm("mov.b64 %0,{%1,%2};" : "=l"(r) : "f"(lo), "f"(hi)); return r;
}
__device__ __forceinline__ void f2upk(u64 a, float& lo, float& hi) {
    asm("mov.b64 {%0,%1},%2;" : "=f"(lo), "=f"(hi) : "l"(a));
}
__device__ __forceinline__ u64 f2add(u64 a, u64 b) {
    u64 d; asm("add.rn.f32x2 %0,%1,%2;" : "=l"(d) : "l"(a), "l"(b)); return d;
}
__device__ __forceinline__ u64 f2mul(u64 a, u64 b) {
    u64 d; asm("mul.rn.f32x2 %0,%1,%2;" : "=l"(d) : "l"(a), "l"(b)); return d;
}
__device__ __forceinline__ u64 f2fma(u64 a, u64 b, u64 c) {
    u64 d; asm("fma.rn.f32x2 %0,%1,%2,%3;" : "=l"(d) : "l"(a), "l"(b), "l"(c)); return d;
}

// Fast tanh via MUFU.EX2 + fast divide. |rel err| ~1e-6.
// e = exp(-2|a|) in (0,1] (no overflow); tanh(|a|) = (1-e)/(1+e); restore sign.
__device__ __forceinline__ float fast_tanh(float a) {
    float e = __expf(-2.0f * fabsf(a));
    float t = __fdividef(1.0f - e, 1.0f + e);
    return copysignf(t, a);
}

// Packed QP state (one sample): x, tau*l2 packed; m = -tau*l1 scalar.
struct QPP {
    u64 xp[4], l2p[4];       // state
    u64 zp[4], czp[4];       // constants
    u64 sb2p[3];             // tau^2 * b packed
    float m[6];              // -tau * l1
};

__device__ __forceinline__ void qp_iter(QPP& q) {
    const float tau  = 0.9f / sqrtf(26.0f);
    const float tau2 = tau * tau;
    const u64 NEG1 = 0xBF800000BF800000ULL;
    const u64 NT2  = f2pk(-tau2, -tau2);

    float m0 = q.m[0], m1 = q.m[1], m2 = q.m[2];
    float m3 = q.m[3], m4 = q.m[4], m5 = q.m[5];

    // sv'' = -tau * S^T l1 (<=0), packed pairs
    // cols: 0:{0,3} 1:{1,4} 2:{2,5} 3:{0,1,5} 4:{2,3,5} 5:{0,3} 6:{1,4} 7:{2,4}
    u64 s01 = f2add(f2pk(m0, m1), f2pk(m3, m4));       // (sv0, sv1)
    float t01 = m0 + m1;
    u64 s23 = f2add(f2pk(m2, t01), f2pk(m5, m5));      // (sv2, sv3)
    float t23 = m2 + m3;
    float sv4 = t23 + m5;
    float sv0, sv1; f2upk(s01, sv0, sv1);
    u64 s45 = f2pk(sv4, sv0);                          // (sv4, sv5=sv0)
    u64 s67 = f2add(f2pk(m1, m2), f2pk(m4, m4));       // (sv6=sv1, sv7)

    // v = (x + cz) + (L2' + sv'')
    u64 v0 = f2add(f2add(q.xp[0], q.czp[0]), f2add(q.l2p[0], s01));
    u64 v1 = f2add(f2add(q.xp[1], q.czp[1]), f2add(q.l2p[1], s23));
    u64 v2 = f2add(f2add(q.xp[2], q.czp[2]), f2add(q.l2p[2], s45));
    u64 v3 = f2add(f2add(q.xp[3], q.czp[3]), f2add(q.l2p[3], s67));

    // ||v||^2  (balanced tree)
    u64 na_ = f2fma(v1, v1, f2mul(v0, v0));
    u64 nb_ = f2fma(v3, v3, f2mul(v2, v2));
    u64 nm  = f2add(na_, nb_);
    float na, nb; f2upk(nm, na, nb);
    float ss = na + nb;

    // scale = max(1 - tau/||v||, 0); rsqrt(0)=inf -> clamps to 0
    float r = rsqrtf(ss);
    float scale = fmaxf(fmaf(-tau, r, 1.0f), 0.0f);
    u64 sc2 = f2pk(scale, scale);

    // xn = z + scale*v ; xb = 2*xn - x
    u64 xn0 = f2fma(v0, sc2, q.zp[0]);
    u64 xn1 = f2fma(v1, sc2, q.zp[1]);
    u64 xn2 = f2fma(v2, sc2, q.zp[2]);
    u64 xn3 = f2fma(v3, sc2, q.zp[3]);
    u64 xb0 = f2add(xn0, f2fma(q.xp[0], NEG1, xn0));
    u64 xb1 = f2add(xn1, f2fma(q.xp[1], NEG1, xn1));
    u64 xb2 = f2add(xn2, f2fma(q.xp[2], NEG1, xn2));
    u64 xb3 = f2add(xn3, f2fma(q.xp[3], NEG1, xn3));
    q.xp[0] = xn0; q.xp[1] = xn1; q.xp[2] = xn2; q.xp[3] = xn3;

    float e0, e1, e2, e3, e4, e5, e6, e7;
    f2upk(xb0, e0, e1); f2upk(xb1, e2, e3);
    f2upk(xb2, e4, e5); f2upk(xb3, e6, e7);

    // rr = S @ xb, rows: 0:{0,3,5} 1:{1,3,6} 2:{2,4,7} 3:{0,4,5} 4:{1,6,7} 5:{2,3,4}
    u64 pp = f2add(xb0, f2pk(e5, e6));                 // (p05, p16)
    float p05, p16; f2upk(pp, p05, p16);
    float p24 = e2 + e4;
    u64 rr01 = f2add(pp, f2pk(e3, e3));                // (rr0, rr1)
    u64 rr23 = f2add(f2pk(p24, p05), f2pk(e7, e4));    // (rr2, rr3)
    u64 rr45 = f2add(f2pk(p16, p24), f2pk(e7, e3));    // (rr4, rr5)

    // l1 dual (negated, scaled): m = min(m - tau2*rr + tau2*b, 0)
    u64 u01 = f2add(f2fma(rr01, NT2, f2pk(m0, m1)), q.sb2p[0]);
    u64 u23 = f2add(f2fma(rr23, NT2, f2pk(m2, m3)), q.sb2p[1]);
    u64 u45 = f2add(f2fma(rr45, NT2, f2pk(m4, m5)), q.sb2p[2]);
    float q0, q1, q2, q3, q4, q5;
    f2upk(u01, q0, q1); f2upk(u23, q2, q3); f2upk(u45, q4, q5);
    q.m[0] = fminf(q0, 0.0f); q.m[1] = fminf(q1, 0.0f);
    q.m[2] = fminf(q2, 0.0f); q.m[3] = fminf(q3, 0.0f);
    q.m[4] = fminf(q4, 0.0f); q.m[5] = fminf(q5, 0.0f);

    // l2 dual (scaled): L2' = max(L2' - tau2*xb, 0)
    {
        u64 w0 = f2fma(xb0, NT2, q.l2p[0]);
        u64 w1 = f2fma(xb1, NT2, q.l2p[1]);
        u64 w2 = f2fma(xb2, NT2, q.l2p[2]);
        u64 w3 = f2fma(xb3, NT2, q.l2p[3]);
        float a, b;
        f2upk(w0, a, b); q.l2p[0] = f2pk(fmaxf(a, 0.f), fmaxf(b, 0.f));
        f2upk(w1, a, b); q.l2p[1] = f2pk(fmaxf(a, 0.f), fmaxf(b, 0.f));
        f2upk(w2, a, b); q.l2p[2] = f2pk(fmaxf(a, 0.f), fmaxf(b, 0.f));
        f2upk(w3, a, b); q.l2p[3] = f2pk(fmaxf(a, 0.f), fmaxf(b, 0.f));
    }
}

// Max |delta| between saved and current state.
__device__ __forceinline__ float qp_delta(const QPP& q,
    const u64 ox[4], const u64 ol[4], const float om[6])
{
    const u64 NEG1 = 0xBF800000BF800000ULL;
    float d = 0.f, a, b;
#pragma unroll
    for (int k = 0; k < 4; ++k) {
        u64 dx = f2fma(ox[k], NEG1, q.xp[k]);
        f2upk(dx, a, b);
        d = fmaxf(d, fmaxf(fabsf(a), fabsf(b)));
        u64 dl = f2fma(ol[k], NEG1, q.l2p[k]);
        f2upk(dl, a, b);
        d = fmaxf(d, fmaxf(fabsf(a), fabsf(b)));
    }
#pragma unroll
    for (int i = 0; i < 6; ++i) d = fmaxf(d, fabsf(q.m[i] - om[i]));
    return d;
}

__global__ void __launch_bounds__(128, 1) matchnet_kernel(
    const float* __restrict__ X,
    const float* __restrict__ W1, const float* __restrict__ b1,
    const float* __restrict__ W2, const float* __restrict__ b2,
    const float* __restrict__ W3, const float* __restrict__ b3,
    const float* __restrict__ W4, const float* __restrict__ b4,
    float* __restrict__ out, int B)
{
    __shared__ __align__(16) float sW1[120];
    __shared__ __align__(16) float sW2[400];
    __shared__ __align__(16) float sW3[400];
    __shared__ __align__(16) float sW4[160];
    __shared__ float sb1[20], sb2s[20], sb3[20], sb4[8];

    const int t = threadIdx.x;
    for (int i = t; i < 120; i += 128) sW1[i] = W1[i];
    for (int i = t; i < 400; i += 128) sW2[i] = W2[i];
    for (int i = t; i < 400; i += 128) sW3[i] = W3[i];
    for (int i = t; i < 160; i += 128) sW4[i] = W4[i];
    if (t < 20) { sb1[t] = b1[t]; sb2s[t] = b2[t]; sb3[t] = b3[t]; }
    if (t < 8)  { sb4[t] = b4[t]; }
    __syncthreads();

    const int idx = blockIdx.x * 128 + t;
    if (idx >= B) return;

    // ---- load bids ----
    float Z[6];
    {
        const float2* Xp = reinterpret_cast<const float2*>(X + (size_t)idx * 6);
        float2 a0 = Xp[0], a1 = Xp[1], a2 = Xp[2];
        Z[0] = a0.x; Z[1] = a0.y; Z[2] = a1.x; Z[3] = a1.y; Z[4] = a2.x; Z[5] = a2.y;
    }

    // ---- MLP 6->20->20->20->8 (fast tanh) ----
    float h1[20], h2[20];
#pragma unroll
    for (int o = 0; o < 20; ++o) {
        const float2* w = reinterpret_cast<const float2*>(&sW1[o * 6]);
        float2 w0 = w[0], w1 = w[1], w2 = w[2];
        float a = sb1[o];
        a = fmaf(w0.x, Z[0], a); a = fmaf(w0.y, Z[1], a);
        a = fmaf(w1.x, Z[2], a); a = fmaf(w1.y, Z[3], a);
        a = fmaf(w2.x, Z[4], a); a = fmaf(w2.y, Z[5], a);
        h1[o] = fast_tanh(a);
    }
#pragma unroll
    for (int o = 0; o < 20; ++o) {
        const float4* w = reinterpret_cast<const float4*>(&sW2[o * 20]);
        float a = sb2s[o];
#pragma unroll
        for (int qq = 0; qq < 5; ++qq) {
            float4 wq = w[qq];
            a = fmaf(wq.x, h1[qq * 4 + 0], a);
            a = fmaf(wq.y, h1[qq * 4 + 1], a);
            a = fmaf(wq.z, h1[qq * 4 + 2], a);
            a = fmaf(wq.w, h1[qq * 4 + 3], a);
        }
        h2[o] = fast_tanh(a);
    }
#pragma unroll
    for (int o = 0; o < 20; ++o) {
        const float4* w = reinterpret_cast<const float4*>(&sW3[o * 20]);
        float a = sb3[o];
#pragma unroll
        for (int qq = 0; qq < 5; ++qq) {
            float4 wq = w[qq];
            a = fmaf(wq.x, h2[qq * 4 + 0], a);
            a = fmaf(wq.y, h2[qq * 4 + 1], a);
            a = fmaf(wq.z, h2[qq * 4 + 2], a);
            a = fmaf(wq.w, h2[qq * 4 + 3], a);
        }
        h1[o] = fast_tanh(a);
    }
    float z[8];
#pragma unroll
    for (int o = 0; o < 8; ++o) {
        const float4* w = reinterpret_cast<const float4*>(&sW4[o * 20]);
        float a = sb4[o];
#pragma unroll
        for (int qq = 0; qq < 5; ++qq) {
            float4 wq = w[qq];
            a = fmaf(wq.x, h1[qq * 4 + 0], a);
            a = fmaf(wq.y, h1[qq * 4 + 1], a);
            a = fmaf(wq.z, h1[qq * 4 + 2], a);
            a = fmaf(wq.w, h1[qq * 4 + 3], a);
        }
        z[o] = fast_tanh(a);
    }

    // ---- QP init (packed, duals scaled by tau) ----
    const float tau  = 0.9f / sqrtf(26.0f);
    const float tau2 = tau * tau;

    QPP q;
#pragma unroll
    for (int k = 0; k < 4; ++k) {
        float zl = z[2 * k], zh = z[2 * k + 1];
        q.zp[k]  = f2pk(zl, zh);
        q.czp[k] = f2pk(tau - zl, tau - zh);
        q.xp[k]  = f2pk(fmaxf(zl, 0.0f), fmaxf(zh, 0.0f));
        q.l2p[k] = 0ULL;
    }
    q.sb2p[0] = f2pk(tau2 * Z[0], tau2 * Z[1]);
    q.sb2p[1] = f2pk(tau2 * Z[2], tau2 * Z[3]);
    q.sb2p[2] = f2pk(tau2 * Z[4], tau2 * Z[5]);
#pragma unroll
    for (int i = 0; i < 6; ++i) q.m[i] = 0.0f;

    // ---- PDHG: 22 plain iters + 16 blocks of (7 plain + 1 checked) = 150 ----
#pragma unroll 1
    for (int it = 0; it < 22; ++it) qp_iter(q);

#pragma unroll 1
    for (int blk = 0; blk < 16; ++blk) {
        qp_iter(q); qp_iter(q); qp_iter(q); qp_iter(q);
        qp_iter(q); qp_iter(q); qp_iter(q);
        u64 ox[4], ol[4]; float om[6];
#pragma unroll
        for (int k = 0; k < 4; ++k) { ox[k] = q.xp[k]; ol[k] = q.l2p[k]; }
#pragma unroll
        for (int i = 0; i < 6; ++i) om[i] = q.m[i];
        qp_iter(q);
        float d = qp_delta(q, ox, ol, om);
        // Non-expansive iteration: per-iter change < 1e-6 for all lanes bounds
        // total remaining drift by 150e-6 = 1.5e-4 << 1e-3 tolerance.
        if (__all_sync(0xFFFFFFFFu, d < 1e-6f)) break;
    }

    // ---- store ----
    float o0, o1, o2, o3, o4, o5, o6, o7;
    f2upk(q.xp[0], o0, o1); f2upk(q.xp[1], o2, o3);
    f2upk(q.xp[2], o4, o5); f2upk(q.xp[3], o6, o7);
    float4* op = reinterpret_cast<float4*>(out + (size_t)idx * 8);
    op[0] = make_float4(o0, o1, o2, o3);
    op[1] = make_float4(o4, o5, o6, o7);
}

extern "C" void kernel_launch(void* const* d_in, const int* in_sizes, int n_in,
                              void* d_out, int out_size)
{
    const float* X  = (const float*)d_in[0];
    const float* W1 = (const float*)d_in[1];
    const float* b1 = (const float*)d_in[2];
    const float* W2 = (const float*)d_in[3];
    const float* b2 = (const float*)d_in[4];
    const float* W3 = (const float*)d_in[5];
    const float* b3 = (const float*)d_in[6];
    const float* W4 = (const float*)d_in[7];
    const float* b4 = (const float*)d_in[8];

    const int B = in_sizes[0] / 6;
    float* out = (float*)d_out;

    const int block = 128;
    const int grid = (B + block - 1) / block;
    matchnet_kernel<<<grid, block>>>(X, W1, b1, W2, b2, W3, b3, W4, b4, out, B);
}

// round 9
// speedup vs baseline: 1.2553x; 1.0478x over previous
#include <cuda_runtime.h>
#include <math.h>

typedef unsigned long long u64;

__device__ __forceinline__ u64 f2pk(float lo, float hi) {
    u64 r; asm("mov.b64 %0,{%1,%2};" : "=l"(r) : "f"(lo), "f"(hi)); return r;
}
__device__ __forceinline__ void f2upk(u64 a, float& lo, float& hi) {
    asm("mov.b64 {%0,%1},%2;" : "=f"(lo), "=f"(hi) : "l"(a));
}
__device__ __forceinline__ u64 f2add(u64 a, u64 b) {
    u64 d; asm("add.rn.f32x2 %0,%1,%2;" : "=l"(d) : "l"(a), "l"(b)); return d;
}
__device__ __forceinline__ u64 f2fma(u64 a, u64 b, u64 c) {
    u64 d; asm("fma.rn.f32x2 %0,%1,%2,%3;" : "=l"(d) : "l"(a), "l"(b), "l"(c)); return d;
}

// Fast tanh via MUFU.EX2 + fast divide. |rel err| ~1e-6.
__device__ __forceinline__ float fast_tanh(float a) {
    float e = __expf(-2.0f * fabsf(a));
    float t = __fdividef(1.0f - e, 1.0f + e);
    return copysignf(t, a);
}

__global__ void __launch_bounds__(128, 1) matchnet_kernel(
    const float* __restrict__ X,
    const float* __restrict__ W1, const float* __restrict__ b1,
    const float* __restrict__ W2, const float* __restrict__ b2,
    const float* __restrict__ W3, const float* __restrict__ b3,
    const float* __restrict__ W4, const float* __restrict__ b4,
    float* __restrict__ out, int B)
{
    __shared__ __align__(16) float sW1[120];
    __shared__ __align__(16) float sW2[400];
    __shared__ __align__(16) float sW3[400];
    __shared__ __align__(16) float sW4[160];
    __shared__ float sb1[20], sb2s[20], sb3[20], sb4[8];

    const int t = threadIdx.x;
    for (int i = t; i < 120; i += 128) sW1[i] = W1[i];
    for (int i = t; i < 400; i += 128) sW2[i] = W2[i];
    for (int i = t; i < 400; i += 128) sW3[i] = W3[i];
    for (int i = t; i < 160; i += 128) sW4[i] = W4[i];
    if (t < 20) { sb1[t] = b1[t]; sb2s[t] = b2[t]; sb3[t] = b3[t]; }
    if (t < 8)  { sb4[t] = b4[t]; }
    __syncthreads();

    const int idx = blockIdx.x * 128 + t;
    if (idx >= B) return;

    // ---- load bids Z ----
    float Z[6];
    {
        const float2* Xp = reinterpret_cast<const float2*>(X + (size_t)idx * 6);
        float2 a0 = Xp[0], a1 = Xp[1], a2 = Xp[2];
        Z[0] = a0.x; Z[1] = a0.y; Z[2] = a1.x; Z[3] = a1.y; Z[4] = a2.x; Z[5] = a2.y;
    }

    // ---- MLP 6->20->20->20->8 (fast tanh) ----
    float h1[20], h2[20];
#pragma unroll
    for (int o = 0; o < 20; ++o) {
        const float2* w = reinterpret_cast<const float2*>(&sW1[o * 6]);
        float2 w0 = w[0], w1 = w[1], w2 = w[2];
        float a = sb1[o];
        a = fmaf(w0.x, Z[0], a); a = fmaf(w0.y, Z[1], a);
        a = fmaf(w1.x, Z[2], a); a = fmaf(w1.y, Z[3], a);
        a = fmaf(w2.x, Z[4], a); a = fmaf(w2.y, Z[5], a);
        h1[o] = fast_tanh(a);
    }
#pragma unroll
    for (int o = 0; o < 20; ++o) {
        const float4* w = reinterpret_cast<const float4*>(&sW2[o * 20]);
        float a = sb2s[o];
#pragma unroll
        for (int qq = 0; qq < 5; ++qq) {
            float4 wq = w[qq];
            a = fmaf(wq.x, h1[qq * 4 + 0], a);
            a = fmaf(wq.y, h1[qq * 4 + 1], a);
            a = fmaf(wq.z, h1[qq * 4 + 2], a);
            a = fmaf(wq.w, h1[qq * 4 + 3], a);
        }
        h2[o] = fast_tanh(a);
    }
#pragma unroll
    for (int o = 0; o < 20; ++o) {
        const float4* w = reinterpret_cast<const float4*>(&sW3[o * 20]);
        float a = sb3[o];
#pragma unroll
        for (int qq = 0; qq < 5; ++qq) {
            float4 wq = w[qq];
            a = fmaf(wq.x, h2[qq * 4 + 0], a);
            a = fmaf(wq.y, h2[qq * 4 + 1], a);
            a = fmaf(wq.z, h2[qq * 4 + 2], a);
            a = fmaf(wq.w, h2[qq * 4 + 3], a);
        }
        h1[o] = fast_tanh(a);
    }
    float z[8];
#pragma unroll
    for (int o = 0; o < 8; ++o) {
        const float4* w = reinterpret_cast<const float4*>(&sW4[o * 20]);
        float a = sb4[o];
#pragma unroll
        for (int qq = 0; qq < 5; ++qq) {
            float4 wq = w[qq];
            a = fmaf(wq.x, h1[qq * 4 + 0], a);
            a = fmaf(wq.y, h1[qq * 4 + 1], a);
            a = fmaf(wq.z, h1[qq * 4 + 2], a);
            a = fmaf(wq.w, h1[qq * 4 + 3], a);
        }
        z[o] = fast_tanh(a);
    }

    // ---- PDHG QP (packed f32x2), duals scaled by tau:
    //      L2' = tau*l2 packed; m = -tau*l1 scalar
    const float tau  = 0.9f / sqrtf(26.0f);
    const float tau2 = tau * tau;
    const u64 NEG1 = 0xBF800000BF800000ULL;
    const u64 NT2  = f2pk(-tau2, -tau2);

    u64 zp[4], czp[4], xp[4], l2p[4];
#pragma unroll
    for (int k = 0; k < 4; ++k) {
        float zl = z[2 * k], zh = z[2 * k + 1];
        zp[k]  = f2pk(zl, zh);
        czp[k] = f2pk(tau - zl, tau - zh);
        xp[k]  = f2pk(fmaxf(zl, 0.0f), fmaxf(zh, 0.0f));
        l2p[k] = 0ULL;
    }
    u64 sb2p[3];
    sb2p[0] = f2pk(tau2 * Z[0], tau2 * Z[1]);
    sb2p[1] = f2pk(tau2 * Z[2], tau2 * Z[3]);
    sb2p[2] = f2pk(tau2 * Z[4], tau2 * Z[5]);
    float m0 = 0.f, m1 = 0.f, m2 = 0.f, m3 = 0.f, m4 = 0.f, m5 = 0.f;

#pragma unroll 1
    for (int it = 0; it < 150; ++it) {
        // sv'' = -tau * S^T l1 (<=0), packed pairs
        // cols: 0:{0,3} 1:{1,4} 2:{2,5} 3:{0,1,5} 4:{2,3,5} 5:{0,3} 6:{1,4} 7:{2,4}
        u64 s01 = f2add(f2pk(m0, m1), f2pk(m3, m4));       // (sv0, sv1)
        float t01 = m0 + m1;
        u64 s23 = f2add(f2pk(m2, t01), f2pk(m5, m5));      // (sv2, sv3)
        float t23 = m2 + m3;
        float sv4 = t23 + m5;
        float sv0, sv1; f2upk(s01, sv0, sv1);
        u64 s45 = f2pk(sv4, sv0);                          // (sv4, sv5=sv0)
        u64 s67 = f2add(f2pk(m1, m2), f2pk(m4, m4));       // (sv6=sv1, sv7)

        // v = (x + cz) + (L2' + sv'')
        u64 v0 = f2add(f2add(xp[0], czp[0]), f2add(l2p[0], s01));
        u64 v1 = f2add(f2add(xp[1], czp[1]), f2add(l2p[1], s23));
        u64 v2 = f2add(f2add(xp[2], czp[2]), f2add(l2p[2], s45));
        u64 v3 = f2add(f2add(xp[3], czp[3]), f2add(l2p[3], s67));

        // ||v||^2 scalar (unpacks are alu-pipe movs; saves packed-fma cycles)
        float f0, f1, f2, f3, f4, f5, f6, f7;
        f2upk(v0, f0, f1); f2upk(v1, f2, f3);
        f2upk(v2, f4, f5); f2upk(v3, f6, f7);
        float c0 = f0 * f0;
        c0 = fmaf(f1, f1, c0); c0 = fmaf(f2, f2, c0); c0 = fmaf(f3, f3, c0);
        float c1 = f4 * f4;
        c1 = fmaf(f5, f5, c1); c1 = fmaf(f6, f6, c1); c1 = fmaf(f7, f7, c1);
        float ss = c0 + c1;

        // scale = max(1 - tau/||v||, 0); rsqrt(0)=inf -> clamps to 0
        float r = rsqrtf(ss);
        float scale = fmaxf(fmaf(-tau, r, 1.0f), 0.0f);
        u64 sc2 = f2pk(scale, scale);

        // xn = z + scale*v ; xb = 2*xn - x
        u64 xn0 = f2fma(v0, sc2, zp[0]);
        u64 xn1 = f2fma(v1, sc2, zp[1]);
        u64 xn2 = f2fma(v2, sc2, zp[2]);
        u64 xn3 = f2fma(v3, sc2, zp[3]);
        u64 xb0 = f2add(xn0, f2fma(xp[0], NEG1, xn0));
        u64 xb1 = f2add(xn1, f2fma(xp[1], NEG1, xn1));
        u64 xb2 = f2add(xn2, f2fma(xp[2], NEG1, xn2));
        u64 xb3 = f2add(xn3, f2fma(xp[3], NEG1, xn3));
        xp[0] = xn0; xp[1] = xn1; xp[2] = xn2; xp[3] = xn3;

        float e0, e1, e2, e3, e4, e5, e6, e7;
        f2upk(xb0, e0, e1); f2upk(xb1, e2, e3);
        f2upk(xb2, e4, e5); f2upk(xb3, e6, e7);

        // rr = S @ xb, rows: 0:{0,3,5} 1:{1,3,6} 2:{2,4,7} 3:{0,4,5} 4:{1,6,7} 5:{2,3,4}
        u64 pp = f2add(xb0, f2pk(e5, e6));                 // (p05, p16)
        float p05, p16; f2upk(pp, p05, p16);
        float p24 = e2 + e4;
        u64 rr01 = f2add(pp, f2pk(e3, e3));                // (rr0, rr1)
        u64 rr23 = f2add(f2pk(p24, p05), f2pk(e7, e4));    // (rr2, rr3)
        u64 rr45 = f2add(f2pk(p16, p24), f2pk(e7, e3));    // (rr4, rr5)

        // l1 dual (negated, scaled): m = min(m - tau2*rr + tau2*b, 0)
        u64 u01 = f2add(f2fma(rr01, NT2, f2pk(m0, m1)), sb2p[0]);
        u64 u23 = f2add(f2fma(rr23, NT2, f2pk(m2, m3)), sb2p[1]);
        u64 u45 = f2add(f2fma(rr45, NT2, f2pk(m4, m5)), sb2p[2]);
        float q0, q1, q2, q3, q4, q5;
        f2upk(u01, q0, q1); f2upk(u23, q2, q3); f2upk(u45, q4, q5);
        m0 = fminf(q0, 0.0f); m1 = fminf(q1, 0.0f); m2 = fminf(q2, 0.0f);
        m3 = fminf(q3, 0.0f); m4 = fminf(q4, 0.0f); m5 = fminf(q5, 0.0f);

        // l2 dual (scaled): L2' = max(L2' - tau2*xb, 0)
        {
            u64 w0 = f2fma(xb0, NT2, l2p[0]);
            u64 w1 = f2fma(xb1, NT2, l2p[1]);
            u64 w2 = f2fma(xb2, NT2, l2p[2]);
            u64 w3 = f2fma(xb3, NT2, l2p[3]);
            float a, b;
            f2upk(w0, a, b); l2p[0] = f2pk(fmaxf(a, 0.f), fmaxf(b, 0.f));
            f2upk(w1, a, b); l2p[1] = f2pk(fmaxf(a, 0.f), fmaxf(b, 0.f));
            f2upk(w2, a, b); l2p[2] = f2pk(fmaxf(a, 0.f), fmaxf(b, 0.f));
            f2upk(w3, a, b); l2p[3] = f2pk(fmaxf(a, 0.f), fmaxf(b, 0.f));
        }
    }

    // ---- store ----
    float o0, o1, o2, o3, o4, o5, o6, o7;
    f2upk(xp[0], o0, o1); f2upk(xp[1], o2, o3);
    f2upk(xp[2], o4, o5); f2upk(xp[3], o6, o7);
    float4* op = reinterpret_cast<float4*>(out + (size_t)idx * 8);
    op[0] = make_float4(o0, o1, o2, o3);
    op[1] = make_float4(o4, o5, o6, o7);
}

extern "C" void kernel_launch(void* const* d_in, const int* in_sizes, int n_in,
                              void* d_out, int out_size)
{
    const float* X  = (const float*)d_in[0];
    const float* W1 = (const float*)d_in[1];
    const float* b1 = (const float*)d_in[2];
    const float* W2 = (const float*)d_in[3];
    const float* b2 = (const float*)d_in[4];
    const float* W3 = (const float*)d_in[5];
    const float* b3 = (const float*)d_in[6];
    const float* W4 = (const float*)d_in[7];
    const float* b4 = (const float*)d_in[8];

    const int B = in_sizes[0] / 6;
    float* out = (float*)d_out;

    const int block = 128;
    const int grid = (B + block - 1) / block;
    matchnet_kernel<<<grid, block>>>(X, W1, b1, W2, b2, W3, b3, W4, b4, out, B);
}